// round 16
// baseline (speedup 1.0000x reference)
#include <cuda_runtime.h>
#include <stdint.h>
#include <math_constants.h>

#define NB   16
#define NP   2000
#define NSORT 2048
#define NG   100
#define IH   160
#define IW   160
#define MHH  28
#define MWW  28
#define NPOS 66
#define NNEG 134
#define TR   200
#define RMAX 52

#define ROIS_OFF 0
#define CLS_OFF  (NB*TR*4)            /* 12800 */
#define DLT_OFF  (CLS_OFF + NB*TR)    /* 16000 */
#define MSK_OFF  (DLT_OFF + NB*TR*4)  /* 28800 */

__device__ float g_pbox[NB*NPOS*4];
__device__ int   g_gidx[NB*NPOS];
__device__ int   g_pval[NB*NPOS];

__device__ unsigned long long g_keyp[NB*NSORT];
__device__ unsigned long long g_keyn[NB*NSORT];

// ---------------- Threefry-2x32 ----------------
__device__ __forceinline__ void tf(uint32_t k0, uint32_t k1, uint32_t& x0, uint32_t& x1) {
    uint32_t k2 = k0 ^ k1 ^ 0x1BD11BDAu;
    x0 += k0; x1 += k1;
#define RND(r) { x0 += x1; x1 = (x1 << (r)) | (x1 >> (32 - (r))); x1 ^= x0; }
    RND(13) RND(15) RND(26) RND(6)
    x0 += k1; x1 += k2 + 1u;
    RND(17) RND(29) RND(16) RND(24)
    x0 += k2; x1 += k0 + 2u;
    RND(13) RND(15) RND(26) RND(6)
    x0 += k0; x1 += k1 + 3u;
    RND(17) RND(29) RND(16) RND(24)
    x0 += k1; x1 += k2 + 4u;
    RND(13) RND(15) RND(26) RND(6)
    x0 += k2; x1 += k0 + 5u;
#undef RND
}

// jax.random.uniform(key,(2000,)) element p — threefry_partitionable=True path.
__device__ __forceinline__ float jax_unif(uint32_t k0, uint32_t k1, int p) {
    uint32_t x0 = 0u, x1 = (uint32_t)p;
    tf(k0, k1, x0, x1);
    uint32_t bits = x0 ^ x1;
    float f = __uint_as_float((bits >> 9) | 0x3F800000u) - 1.0f;
    return fmaxf(0.0f, f);
}

// Order-preserving float->uint32 map (total order, ascending).
__device__ __forceinline__ uint32_t ford(float f) {
    uint32_t b = __float_as_uint(f);
    return (b & 0x80000000u) ? ~b : (b | 0x80000000u);
}

// ---------------- IoU (unfused rounding to match XLA elementwise) ----------
__device__ __forceinline__ float iou_f(float4 p, float4 g) {
    float yA = fmaxf(p.x, g.x), xA = fmaxf(p.y, g.y);
    float yB = fminf(p.z, g.z), xB = fminf(p.w, g.w);
    float ih = fmaxf(__fsub_rn(yB, yA), 0.0f);
    float iw = fmaxf(__fsub_rn(xB, xA), 0.0f);
    float inter = __fmul_rn(ih, iw);
    float a1 = __fmul_rn(__fsub_rn(p.z, p.x), __fsub_rn(p.w, p.y));
    float a2 = __fmul_rn(__fsub_rn(g.z, g.x), __fsub_rn(g.w, g.y));
    float uni = __fsub_rn(__fadd_rn(a1, a2), inter);
    return __fdiv_rn(inter, fmaxf(uni, 1e-10f));
}

// ---------------- kScore: division-free threshold test + fused zero-fill ---
// blocks x<64: scoring. blocks x>=64: zero the negative-slot mask region.
__global__ __launch_bounds__(256) void kScore(const float* __restrict__ prop,
                                              const int*   __restrict__ gcls,
                                              const float* __restrict__ gbox,
                                              float* __restrict__ out) {
    const int b = blockIdx.y;
    const int tid = threadIdx.x;

    if (blockIdx.x >= 64) {
        // zero duty: 26 blocks x 256 threads cover 26264 float4
        const int n4 = (NNEG * MHH * MWW) / 4;
        float4* dst = (float4*)(out + (size_t)MSK_OFF + ((size_t)b * TR + NPOS) * (MHH * MWW));
        for (int i = (blockIdx.x - 64) * 256 + tid; i < n4; i += 26 * 256)
            dst[i] = make_float4(0.f, 0.f, 0.f, 0.f);
        return;
    }

    const int q  = tid & 7;
    const int p  = blockIdx.x * 32 + (tid >> 3);   // 64*32 = 2048 = NSORT

    __shared__ float4 s_gt[NG];
    __shared__ float  s_a2[NG];
    __shared__ uint32_t s_keys[4];

    for (int g = tid; g < NG; g += 256) {
        const float* gp = gbox + ((size_t)b * NG + g) * 4;
        bool gv = (gcls[b * NG + g] > 0);
        float4 gb = gv ? make_float4(gp[0], gp[1], gp[2], gp[3])
                       : make_float4(CUDART_INF_F, CUDART_INF_F, CUDART_INF_F, CUDART_INF_F);
        s_gt[g] = gb;
        s_a2[g] = __fmul_rn(__fsub_rn(gb.z, gb.x), __fsub_rn(gb.w, gb.y)); // NaN if invalid
    }
    if (tid == 0) {
        uint32_t kb0 = 0u, kb1 = (uint32_t)b;
        tf(0u, 42u, kb0, kb1);
        uint32_t p0 = 0u, p1 = 0u; tf(kb0, kb1, p0, p1);
        uint32_t n0 = 0u, n1 = 1u; tf(kb0, kb1, n0, n1);
        s_keys[0] = p0; s_keys[1] = p1;
        s_keys[2] = n0; s_keys[3] = n1;
    }
    __syncthreads();

    const float GUARD = __uint_as_float(0x3F7FFFFFu);   // 1 - 2^-23

    unsigned long long keyp = 0ull, keyn = 0ull;
    if (p < NP) {
        float4 pb = ((const float4*)(prop + (size_t)b * NP * 4))[p];
        float a1 = __fmul_rn(__fsub_rn(pb.z, pb.x), __fsub_rn(pb.w, pb.y));
        bool pos = false;
        #pragma unroll
        for (int g = q; g < NG; g += 8) {
            float4 gb = s_gt[g];
            float yA = fmaxf(pb.x, gb.x), xA = fmaxf(pb.y, gb.y);
            float yB = fminf(pb.z, gb.z), xB = fminf(pb.w, gb.w);
            float ih = fmaxf(__fsub_rn(yB, yA), 0.0f);
            float iw = fmaxf(__fsub_rn(xB, xA), 0.0f);
            float inter = __fmul_rn(ih, iw);
            float uni = fmaxf(__fsub_rn(__fadd_rn(a1, s_a2[g]), inter), 1e-10f);
            float halfu = __fmul_rn(0.5f, uni);
            if (inter >= halfu) {
                pos = true;
            } else if (inter >= __fmul_rn(halfu, GUARD)) {
                if (__fdiv_rn(inter, uni) >= 0.5f) pos = true;
            }
        }
        unsigned pm = __ballot_sync(0xFFFFFFFFu, pos);
        pos = (pm >> (tid & 24)) & 0xFFu;

        if (q == 0) {
            bool vp = (pb.x != 0.0f) || (pb.y != 0.0f) || (pb.z != 0.0f) || (pb.w != 0.0f);
            bool neg = !pos && vp;
            bool posv = pos && vp;
            float sp = posv ? jax_unif(s_keys[0], s_keys[1], p) : -1.0f;
            float sn = neg  ? jax_unif(s_keys[2], s_keys[3], p) : -1.0f;
            uint32_t low = (uint32_t)(NP - 1 - p);
            keyp = ((unsigned long long)ford(sp) << 32) | low;
            keyn = ((unsigned long long)ford(sn) << 32) | low;
        }
    }
    if (q == 0) {
        g_keyp[(size_t)b * NSORT + p] = keyp;
        g_keyn[(size_t)b * NSORT + p] = keyn;
    }
}

// ---------------- kSortEpi: hybrid shuffle bitonic + fused epilogue --------
__global__ __launch_bounds__(1024) void kSortEpi(const float* __restrict__ prop,
                                                 const int*   __restrict__ gcls,
                                                 const float* __restrict__ gbox,
                                                 const float* __restrict__ stdv,
                                                 float* __restrict__ out) {
    const int b = blockIdx.y;
    const bool dop = (blockIdx.x == 0);
    const int tid = threadIdx.x;
    const int w = tid >> 5, l = tid & 31;
    const int e0 = (w << 6) + l;
    const int e1 = e0 + 32;

    __shared__ unsigned long long s_key[NSORT];
    __shared__ float4 s_gt[NG];
    __shared__ int    s_gtv[NG];

    const unsigned long long* src = (dop ? g_keyp : g_keyn) + (size_t)b * NSORT;
    const unsigned long long* srcp = g_keyp + (size_t)b * NSORT;

    int pred[2];
    #pragma unroll
    for (int h = 0; h < 2; h++) {
        int i = tid + h * 1024;
        s_key[i] = src[i];
        pred[h] = ((uint32_t)(srcp[i] >> 32) > 0x80000000u) ? 1 : 0;
    }
    if (dop) {
        for (int g = tid; g < NG; g += 1024) {
            const float* gp = gbox + ((size_t)b * NG + g) * 4;
            s_gt[g] = make_float4(gp[0], gp[1], gp[2], gp[3]);
            s_gtv[g] = (gcls[b * NG + g] > 0) ? 1 : 0;
        }
    }
    int cnt = __syncthreads_count(pred[0]);
    cnt += __syncthreads_count(pred[1]);
    int P = min(cnt, NPOS);
    // XLA lowers x/0.33f to x * (1/0.33f): P=66 -> 200.0 -> nn=134.
    constexpr float RCP33 = 1.0f / 0.33f;
    int nn = (int)(__fmul_rn((float)P, RCP33)) - P;
    nn = max(0, min(nn, NNEG));

    unsigned long long r0, r1;

    #define SHFL_STAGE(k, j) {                                                  \
        unsigned long long p0 = __shfl_xor_sync(0xFFFFFFFFu, r0, (j));          \
        unsigned long long p1 = __shfl_xor_sync(0xFFFFFFFFu, r1, (j));          \
        bool km0 = (((e0 & (k)) == 0) == ((e0 & (j)) == 0));                    \
        bool km1 = (((e1 & (k)) == 0) == ((e1 & (j)) == 0));                    \
        r0 = km0 ? (r0 > p0 ? r0 : p0) : (r0 < p0 ? r0 : p0);                   \
        r1 = km1 ? (r1 > p1 ? r1 : p1) : (r1 < p1 ? r1 : p1);                   \
    }
    #define INTRA_STAGE(k) {                                                    \
        bool up = ((e0 & (k)) == 0);                                            \
        unsigned long long mx = r0 > r1 ? r0 : r1;                              \
        unsigned long long mn = r0 > r1 ? r1 : r0;                              \
        r0 = up ? mx : mn; r1 = up ? mn : mx;                                   \
    }

    r0 = s_key[e0]; r1 = s_key[e1];
    #pragma unroll
    for (unsigned k = 2; k <= 32; k <<= 1)
        for (unsigned j = k >> 1; j >= 1; j >>= 1) SHFL_STAGE(k, j)
    INTRA_STAGE(64)
    #pragma unroll
    for (unsigned j = 16; j >= 1; j >>= 1) SHFL_STAGE(64, j)
    s_key[e0] = r0; s_key[e1] = r1;

    #pragma unroll
    for (unsigned k = 128; k <= 2048; k <<= 1) {
        for (unsigned j = k >> 1; j >= 64; j >>= 1) {
            __syncthreads();
            #pragma unroll
            for (unsigned i = tid; i < NSORT; i += 1024) {
                unsigned ixj = i ^ j;
                if (ixj > i) {
                    unsigned long long a = s_key[i], c = s_key[ixj];
                    bool up = ((i & k) == 0);
                    if (up ? (a < c) : (a > c)) { s_key[i] = c; s_key[ixj] = a; }
                }
            }
        }
        __syncthreads();
        r0 = s_key[e0]; r1 = s_key[e1];
        INTRA_STAGE(k)
        #pragma unroll
        for (unsigned j = 16; j >= 1; j >>= 1) SHFL_STAGE(k, j)
        s_key[e0] = r0; s_key[e1] = r1;
    }
    __syncthreads();
    #undef SHFL_STAGE
    #undef INTRA_STAGE

    const float4* pb4 = (const float4*)(prop + (size_t)b * NP * 4);
    const float sd0 = stdv[0], sd1 = stdv[1], sd2 = stdv[2], sd3 = stdv[3];

    if (dop) {
        if (tid < NPOS * 8) {
            int i = tid >> 3, q = tid & 7;
            unsigned long long key = s_key[i];
            int valid = ((uint32_t)(key >> 32) > 0x80000000u) ? 1 : 0;
            int idx = NP - 1 - (int)(key & 0xFFFFFFFFu);
            float4 pb = pb4[idx];

            float bv = -2.0f; int bg = 0;
            #pragma unroll
            for (int g = q; g < NG; g += 8) {
                float v = s_gtv[g] ? iou_f(pb, s_gt[g]) : -1.0f;
                if (v > bv) { bv = v; bg = g; }
            }
            unsigned mask = 0xFFu << (((tid >> 3) & 3) * 8);
            #pragma unroll
            for (int d = 1; d < 8; d <<= 1) {
                float ov = __shfl_xor_sync(mask, bv, d);
                int   og = __shfl_xor_sync(mask, bg, d);
                if (ov > bv || (ov == bv && og < bg)) { bv = ov; bg = og; }
            }

            if (q == 0) {
                float4 gb = valid ? s_gt[bg] : pb;
                int cls = valid ? gcls[b * NG + bg] : 0;

                float h  = __fsub_rn(pb.z, pb.x), w2 = __fsub_rn(pb.w, pb.y);
                float cy = __fadd_rn(pb.x, __fmul_rn(0.5f, h));
                float cx = __fadd_rn(pb.y, __fmul_rn(0.5f, w2));
                float gh  = __fsub_rn(gb.z, gb.x), gw  = __fsub_rn(gb.w, gb.y);
                float gcy = __fadd_rn(gb.x, __fmul_rn(0.5f, gh));
                float gcx = __fadd_rn(gb.y, __fmul_rn(0.5f, gw));
                float d0 = __fdiv_rn(__fdiv_rn(__fsub_rn(gcy, cy), h), sd0);
                float d1 = __fdiv_rn(__fdiv_rn(__fsub_rn(gcx, cx), w2), sd1);
                float d2 = __fdiv_rn(logf(__fdiv_rn(gh, h)), sd2);
                float d3 = __fdiv_rn(logf(__fdiv_rn(gw, w2)), sd3);

                float fv = valid ? 1.0f : 0.0f;
                size_t ro = (size_t)ROIS_OFF + ((size_t)b * TR + i) * 4;
                out[ro + 0] = __fmul_rn(pb.x, fv);
                out[ro + 1] = __fmul_rn(pb.y, fv);
                out[ro + 2] = __fmul_rn(pb.z, fv);
                out[ro + 3] = __fmul_rn(pb.w, fv);
                out[CLS_OFF + (size_t)b * TR + i] = (float)cls;
                size_t dofs = (size_t)DLT_OFF + ((size_t)b * TR + i) * 4;
                out[dofs + 0] = __fmul_rn(d0, fv);
                out[dofs + 1] = __fmul_rn(d1, fv);
                out[dofs + 2] = __fmul_rn(d2, fv);
                out[dofs + 3] = __fmul_rn(d3, fv);

                int si = b * NPOS + i;
                g_pbox[si * 4 + 0] = pb.x; g_pbox[si * 4 + 1] = pb.y;
                g_pbox[si * 4 + 2] = pb.z; g_pbox[si * 4 + 3] = pb.w;
                g_gidx[si] = bg;
                g_pval[si] = valid;
            }
        }
    } else {
        if (tid < NNEG) {
            int j = tid;
            int slot = NPOS + j;
            unsigned long long key = s_key[j];
            int valid = ((uint32_t)(key >> 32) > 0x80000000u) ? 1 : 0;
            int idx = NP - 1 - (int)(key & 0xFFFFFFFFu);
            float nv = (valid && (j < nn)) ? 1.0f : 0.0f;
            float4 pb = pb4[idx];
            size_t ro = (size_t)ROIS_OFF + ((size_t)b * TR + slot) * 4;
            out[ro + 0] = __fmul_rn(pb.x, nv);
            out[ro + 1] = __fmul_rn(pb.y, nv);
            out[ro + 2] = __fmul_rn(pb.z, nv);
            out[ro + 3] = __fmul_rn(pb.w, nv);
            out[CLS_OFF + (size_t)b * TR + slot] = 0.0f;
            size_t dofs = (size_t)DLT_OFF + ((size_t)b * TR + slot) * 4;
            out[dofs + 0] = 0.0f; out[dofs + 1] = 0.0f;
            out[dofs + 2] = 0.0f; out[dofs + 3] = 0.0f;
        }
    }
}

// ---------------- kBpos: crop_and_resize, smem-staged dedup ----------------
// Stage the ~(span+2)^2 distinct mask pixels once (vs 3136 redundant gathers),
// then sample bilinear from smem. RMAX=52 covers all boxes (y2<=1 -> span<=50).
__global__ __launch_bounds__(800) void kBpos(const float* __restrict__ pmasks,
                                             float* __restrict__ out) {
    const int slot = blockIdx.x;                     // 0..NPOS-1
    const int b = blockIdx.y;
    const int px = threadIdx.x;
    float* o = out + (size_t)MSK_OFF + ((size_t)b * TR + slot) * (MHH * MWW);

    __shared__ float s_img[RMAX * RMAX];

    if (!g_pval[b * NPOS + slot]) {
        if (px < MHH * MWW) o[px] = 0.0f;
        return;                                      // uniform per block
    }

    const int si = b * NPOS + slot;
    const float y1 = g_pbox[si * 4 + 0], x1 = g_pbox[si * 4 + 1];
    const float y2 = g_pbox[si * 4 + 2], x2 = g_pbox[si * 4 + 3];
    const int g = g_gidx[si];
    const float* img = pmasks + (size_t)b * (IH * IW * NG) + g;
    const float dy = __fsub_rn(y2, y1), dx = __fsub_rn(x2, x1);

    // staging region covering all clamped bilinear taps
    int ylo = min(max((int)floorf(__fmul_rn(y1, 159.0f)), 0), IH - 1);
    int xlo = min(max((int)floorf(__fmul_rn(x1, 159.0f)), 0), IW - 1);
    int yhi = min((int)floorf(__fmul_rn(__fadd_rn(y1, dy), 159.0f)) + 2, IH - 1);
    int xhi = min((int)floorf(__fmul_rn(__fadd_rn(x1, dx), 159.0f)) + 2, IW - 1);
    int rows = yhi - ylo + 1, cols = xhi - xlo + 1;
    bool staged = (rows <= RMAX) && (cols <= RMAX);

    if (staged) {
        for (int idx = px; idx < rows * cols; idx += 800) {
            int r = idx / cols, c = idx - r * cols;
            s_img[idx] = img[((size_t)(ylo + r) * IW + (xlo + c)) * NG];
        }
    }
    __syncthreads();

    if (px >= MHH * MWW) return;

    int i = px / MWW, j = px - i * MWW;
    float ty = __fdiv_rn((float)i, 27.0f);
    float tx = __fdiv_rn((float)j, 27.0f);
    float ys = __fmul_rn(__fadd_rn(y1, __fmul_rn(ty, dy)), 159.0f);
    float xs = __fmul_rn(__fadd_rn(x1, __fmul_rn(tx, dx)), 159.0f);
    float y0f = floorf(ys), x0f = floorf(xs);
    float fy = __fsub_rn(ys, y0f), fx = __fsub_rn(xs, x0f);
    int y0 = min(max((int)y0f, 0), IH - 1);
    int x0 = min(max((int)x0f, 0), IW - 1);
    int y1i = min(y0 + 1, IH - 1);
    int x1i = min(x0 + 1, IW - 1);
    float m00, m01, m10, m11;
    if (staged && y0 >= ylo && y1i <= yhi && x0 >= xlo && x1i <= xhi) {
        int ly0 = y0 - ylo, ly1 = y1i - ylo, lx0 = x0 - xlo, lx1 = x1i - xlo;
        m00 = s_img[ly0 * cols + lx0];
        m01 = s_img[ly0 * cols + lx1];
        m10 = s_img[ly1 * cols + lx0];
        m11 = s_img[ly1 * cols + lx1];
    } else {
        m00 = img[((size_t)y0 * IW + x0) * NG];
        m01 = img[((size_t)y0 * IW + x1i) * NG];
        m10 = img[((size_t)y1i * IW + x0) * NG];
        m11 = img[((size_t)y1i * IW + x1i) * NG];
    }
    float ofy = __fsub_rn(1.0f, fy), ofx = __fsub_rn(1.0f, fx);
    float v = __fadd_rn(__fadd_rn(__fadd_rn(
                __fmul_rn(__fmul_rn(m00, ofy), ofx),
                __fmul_rn(__fmul_rn(m01, ofy), fx)),
                __fmul_rn(__fmul_rn(m10, fy), ofx)),
                __fmul_rn(__fmul_rn(m11, fy), fx));
    o[px] = rintf(v);
}

extern "C" void kernel_launch(void* const* d_in, const int* in_sizes, int n_in,
                              void* d_out, int out_size) {
    const float* prop   = (const float*)d_in[0];
    const int*   gcls   = (const int*)d_in[1];
    const float* gbox   = (const float*)d_in[2];
    const float* pmasks = (const float*)d_in[3];
    const float* stdv   = (const float*)d_in[4];
    float* out = (float*)d_out;

    kScore<<<dim3(90, NB), 256>>>(prop, gcls, gbox, out);
    kSortEpi<<<dim3(2, NB), 1024>>>(prop, gcls, gbox, stdv, out);
    kBpos<<<dim3(NPOS, NB), 800>>>(pmasks, out);
}

// round 17
// speedup vs baseline: 1.1049x; 1.1049x over previous
#include <cuda_runtime.h>
#include <stdint.h>
#include <math_constants.h>

#define NB   16
#define NP   2000
#define NSORT 2048
#define NG   100
#define IH   160
#define IW   160
#define MHH  28
#define MWW  28
#define NPOS 66
#define NNEG 134
#define TR   200

#define ROIS_OFF 0
#define CLS_OFF  (NB*TR*4)            /* 12800 */
#define DLT_OFF  (CLS_OFF + NB*TR)    /* 16000 */
#define MSK_OFF  (DLT_OFF + NB*TR*4)  /* 28800 */

__device__ float g_pbox[NB*NPOS*4];
__device__ int   g_gidx[NB*NPOS];
__device__ int   g_pval[NB*NPOS];

__device__ unsigned long long g_keyp[NB*NSORT];
__device__ unsigned long long g_keyn[NB*NSORT];

// ---------------- Threefry-2x32 ----------------
__device__ __forceinline__ void tf(uint32_t k0, uint32_t k1, uint32_t& x0, uint32_t& x1) {
    uint32_t k2 = k0 ^ k1 ^ 0x1BD11BDAu;
    x0 += k0; x1 += k1;
#define RND(r) { x0 += x1; x1 = (x1 << (r)) | (x1 >> (32 - (r))); x1 ^= x0; }
    RND(13) RND(15) RND(26) RND(6)
    x0 += k1; x1 += k2 + 1u;
    RND(17) RND(29) RND(16) RND(24)
    x0 += k2; x1 += k0 + 2u;
    RND(13) RND(15) RND(26) RND(6)
    x0 += k0; x1 += k1 + 3u;
    RND(17) RND(29) RND(16) RND(24)
    x0 += k1; x1 += k2 + 4u;
    RND(13) RND(15) RND(26) RND(6)
    x0 += k2; x1 += k0 + 5u;
#undef RND
}

// jax.random.uniform(key,(2000,)) element p — threefry_partitionable=True path.
__device__ __forceinline__ float jax_unif(uint32_t k0, uint32_t k1, int p) {
    uint32_t x0 = 0u, x1 = (uint32_t)p;
    tf(k0, k1, x0, x1);
    uint32_t bits = x0 ^ x1;
    float f = __uint_as_float((bits >> 9) | 0x3F800000u) - 1.0f;
    return fmaxf(0.0f, f);
}

// Order-preserving float->uint32 map (total order, ascending).
__device__ __forceinline__ uint32_t ford(float f) {
    uint32_t b = __float_as_uint(f);
    return (b & 0x80000000u) ? ~b : (b | 0x80000000u);
}

// ---------------- IoU (unfused rounding to match XLA elementwise) ----------
__device__ __forceinline__ float iou_f(float4 p, float4 g) {
    float yA = fmaxf(p.x, g.x), xA = fmaxf(p.y, g.y);
    float yB = fminf(p.z, g.z), xB = fminf(p.w, g.w);
    float ih = fmaxf(__fsub_rn(yB, yA), 0.0f);
    float iw = fmaxf(__fsub_rn(xB, xA), 0.0f);
    float inter = __fmul_rn(ih, iw);
    float a1 = __fmul_rn(__fsub_rn(p.z, p.x), __fsub_rn(p.w, p.y));
    float a2 = __fmul_rn(__fsub_rn(g.z, g.x), __fsub_rn(g.w, g.y));
    float uni = __fsub_rn(__fadd_rn(a1, a2), inter);
    return __fdiv_rn(inter, fmaxf(uni, 1e-10f));
}

// ---------------- kScore: division-free threshold test + fused zero-fill ---
// blocks x<64: scoring. blocks x>=64: zero the negative-slot mask region.
__global__ __launch_bounds__(256) void kScore(const float* __restrict__ prop,
                                              const int*   __restrict__ gcls,
                                              const float* __restrict__ gbox,
                                              float* __restrict__ out) {
    const int b = blockIdx.y;
    const int tid = threadIdx.x;

    if (blockIdx.x >= 64) {
        // zero duty: 26 blocks x 256 threads cover 26264 float4
        const int n4 = (NNEG * MHH * MWW) / 4;
        float4* dst = (float4*)(out + (size_t)MSK_OFF + ((size_t)b * TR + NPOS) * (MHH * MWW));
        for (int i = (blockIdx.x - 64) * 256 + tid; i < n4; i += 26 * 256)
            dst[i] = make_float4(0.f, 0.f, 0.f, 0.f);
        return;
    }

    const int q  = tid & 7;
    const int p  = blockIdx.x * 32 + (tid >> 3);   // 64*32 = 2048 = NSORT

    __shared__ float4 s_gt[NG];
    __shared__ float  s_a2[NG];
    __shared__ uint32_t s_keys[4];

    for (int g = tid; g < NG; g += 256) {
        const float* gp = gbox + ((size_t)b * NG + g) * 4;
        bool gv = (gcls[b * NG + g] > 0);
        float4 gb = gv ? make_float4(gp[0], gp[1], gp[2], gp[3])
                       : make_float4(CUDART_INF_F, CUDART_INF_F, CUDART_INF_F, CUDART_INF_F);
        s_gt[g] = gb;
        s_a2[g] = __fmul_rn(__fsub_rn(gb.z, gb.x), __fsub_rn(gb.w, gb.y)); // NaN if invalid
    }
    if (tid == 0) {
        uint32_t kb0 = 0u, kb1 = (uint32_t)b;
        tf(0u, 42u, kb0, kb1);
        uint32_t p0 = 0u, p1 = 0u; tf(kb0, kb1, p0, p1);
        uint32_t n0 = 0u, n1 = 1u; tf(kb0, kb1, n0, n1);
        s_keys[0] = p0; s_keys[1] = p1;
        s_keys[2] = n0; s_keys[3] = n1;
    }
    __syncthreads();

    const float GUARD = __uint_as_float(0x3F7FFFFFu);   // 1 - 2^-23

    unsigned long long keyp = 0ull, keyn = 0ull;
    if (p < NP) {
        float4 pb = ((const float4*)(prop + (size_t)b * NP * 4))[p];
        float a1 = __fmul_rn(__fsub_rn(pb.z, pb.x), __fsub_rn(pb.w, pb.y));
        bool pos = false;
        #pragma unroll
        for (int g = q; g < NG; g += 8) {
            float4 gb = s_gt[g];
            float yA = fmaxf(pb.x, gb.x), xA = fmaxf(pb.y, gb.y);
            float yB = fminf(pb.z, gb.z), xB = fminf(pb.w, gb.w);
            float ih = fmaxf(__fsub_rn(yB, yA), 0.0f);
            float iw = fmaxf(__fsub_rn(xB, xA), 0.0f);
            float inter = __fmul_rn(ih, iw);
            float uni = fmaxf(__fsub_rn(__fadd_rn(a1, s_a2[g]), inter), 1e-10f);
            float halfu = __fmul_rn(0.5f, uni);
            if (inter >= halfu) {
                pos = true;
            } else if (inter >= __fmul_rn(halfu, GUARD)) {
                if (__fdiv_rn(inter, uni) >= 0.5f) pos = true;
            }
        }
        unsigned pm = __ballot_sync(0xFFFFFFFFu, pos);
        pos = (pm >> (tid & 24)) & 0xFFu;

        if (q == 0) {
            bool vp = (pb.x != 0.0f) || (pb.y != 0.0f) || (pb.z != 0.0f) || (pb.w != 0.0f);
            bool neg = !pos && vp;
            bool posv = pos && vp;
            float sp = posv ? jax_unif(s_keys[0], s_keys[1], p) : -1.0f;
            float sn = neg  ? jax_unif(s_keys[2], s_keys[3], p) : -1.0f;
            uint32_t low = (uint32_t)(NP - 1 - p);
            keyp = ((unsigned long long)ford(sp) << 32) | low;
            keyn = ((unsigned long long)ford(sn) << 32) | low;
        }
    }
    if (q == 0) {
        g_keyp[(size_t)b * NSORT + p] = keyp;
        g_keyn[(size_t)b * NSORT + p] = keyn;
    }
}

// ---------------- kSortEpi: hybrid shuffle bitonic + fused epilogue --------
__global__ __launch_bounds__(1024) void kSortEpi(const float* __restrict__ prop,
                                                 const int*   __restrict__ gcls,
                                                 const float* __restrict__ gbox,
                                                 const float* __restrict__ stdv,
                                                 float* __restrict__ out) {
    const int b = blockIdx.y;
    const bool dop = (blockIdx.x == 0);
    const int tid = threadIdx.x;
    const int w = tid >> 5, l = tid & 31;
    const int e0 = (w << 6) + l;
    const int e1 = e0 + 32;

    __shared__ unsigned long long s_key[NSORT];
    __shared__ float4 s_gt[NG];
    __shared__ int    s_gtv[NG];

    const unsigned long long* src = (dop ? g_keyp : g_keyn) + (size_t)b * NSORT;
    const unsigned long long* srcp = g_keyp + (size_t)b * NSORT;

    int pred[2];
    #pragma unroll
    for (int h = 0; h < 2; h++) {
        int i = tid + h * 1024;
        s_key[i] = src[i];
        pred[h] = ((uint32_t)(srcp[i] >> 32) > 0x80000000u) ? 1 : 0;
    }
    if (dop) {
        for (int g = tid; g < NG; g += 1024) {
            const float* gp = gbox + ((size_t)b * NG + g) * 4;
            s_gt[g] = make_float4(gp[0], gp[1], gp[2], gp[3]);
            s_gtv[g] = (gcls[b * NG + g] > 0) ? 1 : 0;
        }
    }
    int cnt = __syncthreads_count(pred[0]);
    cnt += __syncthreads_count(pred[1]);
    int P = min(cnt, NPOS);
    // XLA lowers x/0.33f to x * (1/0.33f): P=66 -> 200.0 -> nn=134.
    constexpr float RCP33 = 1.0f / 0.33f;
    int nn = (int)(__fmul_rn((float)P, RCP33)) - P;
    nn = max(0, min(nn, NNEG));

    unsigned long long r0, r1;

    #define SHFL_STAGE(k, j) {                                                  \
        unsigned long long p0 = __shfl_xor_sync(0xFFFFFFFFu, r0, (j));          \
        unsigned long long p1 = __shfl_xor_sync(0xFFFFFFFFu, r1, (j));          \
        bool km0 = (((e0 & (k)) == 0) == ((e0 & (j)) == 0));                    \
        bool km1 = (((e1 & (k)) == 0) == ((e1 & (j)) == 0));                    \
        r0 = km0 ? (r0 > p0 ? r0 : p0) : (r0 < p0 ? r0 : p0);                   \
        r1 = km1 ? (r1 > p1 ? r1 : p1) : (r1 < p1 ? r1 : p1);                   \
    }
    #define INTRA_STAGE(k) {                                                    \
        bool up = ((e0 & (k)) == 0);                                            \
        unsigned long long mx = r0 > r1 ? r0 : r1;                              \
        unsigned long long mn = r0 > r1 ? r1 : r0;                              \
        r0 = up ? mx : mn; r1 = up ? mn : mx;                                   \
    }

    r0 = s_key[e0]; r1 = s_key[e1];
    #pragma unroll
    for (unsigned k = 2; k <= 32; k <<= 1)
        for (unsigned j = k >> 1; j >= 1; j >>= 1) SHFL_STAGE(k, j)
    INTRA_STAGE(64)
    #pragma unroll
    for (unsigned j = 16; j >= 1; j >>= 1) SHFL_STAGE(64, j)
    s_key[e0] = r0; s_key[e1] = r1;

    #pragma unroll
    for (unsigned k = 128; k <= 2048; k <<= 1) {
        for (unsigned j = k >> 1; j >= 64; j >>= 1) {
            __syncthreads();
            #pragma unroll
            for (unsigned i = tid; i < NSORT; i += 1024) {
                unsigned ixj = i ^ j;
                if (ixj > i) {
                    unsigned long long a = s_key[i], c = s_key[ixj];
                    bool up = ((i & k) == 0);
                    if (up ? (a < c) : (a > c)) { s_key[i] = c; s_key[ixj] = a; }
                }
            }
        }
        __syncthreads();
        r0 = s_key[e0]; r1 = s_key[e1];
        INTRA_STAGE(k)
        #pragma unroll
        for (unsigned j = 16; j >= 1; j >>= 1) SHFL_STAGE(k, j)
        s_key[e0] = r0; s_key[e1] = r1;
    }
    __syncthreads();
    #undef SHFL_STAGE
    #undef INTRA_STAGE

    const float4* pb4 = (const float4*)(prop + (size_t)b * NP * 4);
    const float sd0 = stdv[0], sd1 = stdv[1], sd2 = stdv[2], sd3 = stdv[3];

    if (dop) {
        if (tid < NPOS * 8) {
            int i = tid >> 3, q = tid & 7;
            unsigned long long key = s_key[i];
            int valid = ((uint32_t)(key >> 32) > 0x80000000u) ? 1 : 0;
            int idx = NP - 1 - (int)(key & 0xFFFFFFFFu);
            float4 pb = pb4[idx];

            float bv = -2.0f; int bg = 0;
            #pragma unroll
            for (int g = q; g < NG; g += 8) {
                float v = s_gtv[g] ? iou_f(pb, s_gt[g]) : -1.0f;
                if (v > bv) { bv = v; bg = g; }
            }
            unsigned mask = 0xFFu << (((tid >> 3) & 3) * 8);
            #pragma unroll
            for (int d = 1; d < 8; d <<= 1) {
                float ov = __shfl_xor_sync(mask, bv, d);
                int   og = __shfl_xor_sync(mask, bg, d);
                if (ov > bv || (ov == bv && og < bg)) { bv = ov; bg = og; }
            }

            if (q == 0) {
                float4 gb = valid ? s_gt[bg] : pb;
                int cls = valid ? gcls[b * NG + bg] : 0;

                float h  = __fsub_rn(pb.z, pb.x), w2 = __fsub_rn(pb.w, pb.y);
                float cy = __fadd_rn(pb.x, __fmul_rn(0.5f, h));
                float cx = __fadd_rn(pb.y, __fmul_rn(0.5f, w2));
                float gh  = __fsub_rn(gb.z, gb.x), gw  = __fsub_rn(gb.w, gb.y);
                float gcy = __fadd_rn(gb.x, __fmul_rn(0.5f, gh));
                float gcx = __fadd_rn(gb.y, __fmul_rn(0.5f, gw));
                float d0 = __fdiv_rn(__fdiv_rn(__fsub_rn(gcy, cy), h), sd0);
                float d1 = __fdiv_rn(__fdiv_rn(__fsub_rn(gcx, cx), w2), sd1);
                float d2 = __fdiv_rn(logf(__fdiv_rn(gh, h)), sd2);
                float d3 = __fdiv_rn(logf(__fdiv_rn(gw, w2)), sd3);

                float fv = valid ? 1.0f : 0.0f;
                size_t ro = (size_t)ROIS_OFF + ((size_t)b * TR + i) * 4;
                out[ro + 0] = __fmul_rn(pb.x, fv);
                out[ro + 1] = __fmul_rn(pb.y, fv);
                out[ro + 2] = __fmul_rn(pb.z, fv);
                out[ro + 3] = __fmul_rn(pb.w, fv);
                out[CLS_OFF + (size_t)b * TR + i] = (float)cls;
                size_t dofs = (size_t)DLT_OFF + ((size_t)b * TR + i) * 4;
                out[dofs + 0] = __fmul_rn(d0, fv);
                out[dofs + 1] = __fmul_rn(d1, fv);
                out[dofs + 2] = __fmul_rn(d2, fv);
                out[dofs + 3] = __fmul_rn(d3, fv);

                int si = b * NPOS + i;
                g_pbox[si * 4 + 0] = pb.x; g_pbox[si * 4 + 1] = pb.y;
                g_pbox[si * 4 + 2] = pb.z; g_pbox[si * 4 + 3] = pb.w;
                g_gidx[si] = bg;
                g_pval[si] = valid;
            }
        }
    } else {
        if (tid < NNEG) {
            int j = tid;
            int slot = NPOS + j;
            unsigned long long key = s_key[j];
            int valid = ((uint32_t)(key >> 32) > 0x80000000u) ? 1 : 0;
            int idx = NP - 1 - (int)(key & 0xFFFFFFFFu);
            float nv = (valid && (j < nn)) ? 1.0f : 0.0f;
            float4 pb = pb4[idx];
            size_t ro = (size_t)ROIS_OFF + ((size_t)b * TR + slot) * 4;
            out[ro + 0] = __fmul_rn(pb.x, nv);
            out[ro + 1] = __fmul_rn(pb.y, nv);
            out[ro + 2] = __fmul_rn(pb.z, nv);
            out[ro + 3] = __fmul_rn(pb.w, nv);
            out[CLS_OFF + (size_t)b * TR + slot] = 0.0f;
            size_t dofs = (size_t)DLT_OFF + ((size_t)b * TR + slot) * 4;
            out[dofs + 0] = 0.0f; out[dofs + 1] = 0.0f;
            out[dofs + 2] = 0.0f; out[dofs + 3] = 0.0f;
        }
    }
}

// ---------------- kBpos: mask crop_and_resize, 1 px/thread (direct) --------
__global__ __launch_bounds__(800) void kBpos(const float* __restrict__ pmasks,
                                             float* __restrict__ out) {
    const int slot = blockIdx.x;                     // 0..NPOS-1
    const int b = blockIdx.y;
    const int px = threadIdx.x;
    if (px >= MHH * MWW) return;
    float* o = out + (size_t)MSK_OFF + ((size_t)b * TR + slot) * (MHH * MWW);

    if (!g_pval[b * NPOS + slot]) { o[px] = 0.0f; return; }

    const int si = b * NPOS + slot;
    const float y1 = g_pbox[si * 4 + 0], x1 = g_pbox[si * 4 + 1];
    const float y2 = g_pbox[si * 4 + 2], x2 = g_pbox[si * 4 + 3];
    const int g = g_gidx[si];
    const float* img = pmasks + (size_t)b * (IH * IW * NG) + g;
    const float dy = __fsub_rn(y2, y1), dx = __fsub_rn(x2, x1);

    int i = px / MWW, j = px - i * MWW;
    float ty = __fdiv_rn((float)i, 27.0f);
    float tx = __fdiv_rn((float)j, 27.0f);
    float ys = __fmul_rn(__fadd_rn(y1, __fmul_rn(ty, dy)), 159.0f);
    float xs = __fmul_rn(__fadd_rn(x1, __fmul_rn(tx, dx)), 159.0f);
    float y0f = floorf(ys), x0f = floorf(xs);
    float fy = __fsub_rn(ys, y0f), fx = __fsub_rn(xs, x0f);
    int y0 = min(max((int)y0f, 0), IH - 1);
    int x0 = min(max((int)x0f, 0), IW - 1);
    int y1i = min(y0 + 1, IH - 1);
    int x1i = min(x0 + 1, IW - 1);
    float m00 = img[((size_t)y0 * IW + x0) * NG];
    float m01 = img[((size_t)y0 * IW + x1i) * NG];
    float m10 = img[((size_t)y1i * IW + x0) * NG];
    float m11 = img[((size_t)y1i * IW + x1i) * NG];
    float ofy = __fsub_rn(1.0f, fy), ofx = __fsub_rn(1.0f, fx);
    float v = __fadd_rn(__fadd_rn(__fadd_rn(
                __fmul_rn(__fmul_rn(m00, ofy), ofx),
                __fmul_rn(__fmul_rn(m01, ofy), fx)),
                __fmul_rn(__fmul_rn(m10, fy), ofx)),
                __fmul_rn(__fmul_rn(m11, fy), fx));
    o[px] = rintf(v);
}

extern "C" void kernel_launch(void* const* d_in, const int* in_sizes, int n_in,
                              void* d_out, int out_size) {
    const float* prop   = (const float*)d_in[0];
    const int*   gcls   = (const int*)d_in[1];
    const float* gbox   = (const float*)d_in[2];
    const float* pmasks = (const float*)d_in[3];
    const float* stdv   = (const float*)d_in[4];
    float* out = (float*)d_out;

    kScore<<<dim3(90, NB), 256>>>(prop, gcls, gbox, out);
    kSortEpi<<<dim3(2, NB), 1024>>>(prop, gcls, gbox, stdv, out);
    kBpos<<<dim3(NPOS, NB), 800>>>(pmasks, out);
}